// round 9
// baseline (speedup 1.0000x reference)
#include <cuda_runtime.h>
#include <cuda_fp16.h>
#include <math.h>
#include <stdint.h>
#include <mma.h>

using namespace nvcuda;

#define BATCH 4
#define SEQ   1024
#define DMODEL 4096
#define KVDIM 512
#define NHEAD 32
#define HDIM  128
#define MROWS (BATCH*SEQ)   // 4096

// ---------------- scratch ----------------
__device__ __half g_x[MROWS * DMODEL];
__device__ __half g_wq[DMODEL * DMODEL];
__device__ __half g_wk[DMODEL * KVDIM];
__device__ __half g_wv[DMODEL * KVDIM];
__device__ __half g_wo[DMODEL * DMODEL];
__device__ __half g_Qh[MROWS * DMODEL], g_Ql[MROWS * DMODEL];
__device__ __half g_Kh[MROWS * KVDIM];
__device__ __half g_Vh[MROWS * KVDIM];
__device__ __half g_o[MROWS * DMODEL];
__device__ float2 g_rope[SEQ * 64];

// ---------------- fp32 -> fp16 ----------------
__global__ void conv_half_kernel(const float* __restrict__ src,
                                 __half* __restrict__ dst, int n4)
{
    int idx = blockIdx.x * blockDim.x + threadIdx.x;
    if (idx >= n4) return;
    float4 v = ((const float4*)src)[idx];
    ((__half2*)dst)[idx * 2]     = __halves2half2(__float2half(v.x), __float2half(v.y));
    ((__half2*)dst)[idx * 2 + 1] = __halves2half2(__float2half(v.z), __float2half(v.w));
}

// ---------------- rope table init ----------------
__global__ void rope_init_kernel(float2* __restrict__ T)
{
    int idx = blockIdx.x * blockDim.x + threadIdx.x;
    if (idx >= SEQ * 64) return;
    int pos = idx >> 6;
    int i = idx & 63;
    float freq = exp2f(-(float)i * 0.20762050593434293f);   // log2(10000)/64
    float sv, cv;
    sincosf((float)pos * freq, &sv, &cv);
    T[idx] = make_float2(cv, sv);
}

// ---------------- fp16 GEMM with fused epilogue ----------------
// C = A[M,K] * B[K,N], fp32 acc. BM=BN=128, BK=32, 3-stage cp.async,
// 8 warps (2x4), warp tile 64x32.
// MODE 0: Q  -> bias+rope+scale -> fp16 hi/lo (out0, out1)
// MODE 1: K  -> bias+rope       -> fp16 (out0)
// MODE 2: V  -> bias            -> fp16 (out0)
// MODE 3: out-> bias            -> fp32 (out0)
#define SA_LD 40
#define SB_LD 136
#define STAGE_H (128*SA_LD + 32*SB_LD)
#define GEMM_SMEM (3 * STAGE_H * 2)
#define EP_LD 36   // epilogue staging stride (floats) — MUST be multiple of 4

__device__ __forceinline__ void cp16(void* s, const void* g)
{
    uint32_t sa = (uint32_t)__cvta_generic_to_shared(s);
    asm volatile("cp.async.cg.shared.global [%0], [%1], 16;\n" :: "r"(sa), "l"(g));
}

template<int MODE>
__global__ void __launch_bounds__(256) gemm_ep_kernel(
    const __half* __restrict__ A, const __half* __restrict__ B,
    const float* __restrict__ bias, const float2* __restrict__ rope,
    void* __restrict__ out0, void* __restrict__ out1, int Nn, int K)
{
    extern __shared__ __half smh[];
    const int bm = blockIdx.y * 128;
    const int bn = blockIdx.x * 128;
    const int tid = threadIdx.x;
    const int lane = tid & 31;
    const int warp = tid >> 5;
    const int wr = (warp >> 2) * 64;
    const int wc = (warp & 3) * 32;

    wmma::fragment<wmma::accumulator, 16, 16, 16, float> acc[4][2];
    #pragma unroll
    for (int i = 0; i < 4; i++)
        #pragma unroll
        for (int j = 0; j < 2; j++)
            wmma::fill_fragment(acc[i][j], 0.0f);

    auto load_st = [&](int kt) {
        __half* s = smh + (kt % 3) * STAGE_H;
        int k0 = kt << 5;
        #pragma unroll
        for (int it = 0; it < 2; ++it) {
            int v = tid + it * 256;
            int r = v >> 2, c = (v & 3) << 3;
            cp16(s + r * SA_LD + c, A + (size_t)(bm + r) * K + k0 + c);
            int rb = v >> 4, cb = (v & 15) << 3;
            cp16(s + 128 * SA_LD + rb * SB_LD + cb,
                 B + (size_t)(k0 + rb) * Nn + bn + cb);
        }
        asm volatile("cp.async.commit_group;\n");
    };

    const int nt = K >> 5;
    load_st(0);
    load_st(1);

    for (int kt = 0; kt < nt; ++kt) {
        if (kt + 1 < nt)
            asm volatile("cp.async.wait_group 1;\n");
        else
            asm volatile("cp.async.wait_group 0;\n");
        __syncthreads();
        if (kt + 2 < nt) load_st(kt + 2);

        __half* s  = smh + (kt % 3) * STAGE_H;
        __half* sA = s;
        __half* sB = s + 128 * SA_LD;

        #pragma unroll
        for (int kk = 0; kk < 32; kk += 16) {
            wmma::fragment<wmma::matrix_b, 16, 16, 16, __half, wmma::row_major> b[2];
            #pragma unroll
            for (int j = 0; j < 2; j++)
                wmma::load_matrix_sync(b[j], sB + kk * SB_LD + wc + j * 16, SB_LD);
            #pragma unroll
            for (int i = 0; i < 4; i++) {
                wmma::fragment<wmma::matrix_a, 16, 16, 16, __half, wmma::row_major> a;
                wmma::load_matrix_sync(a, sA + (wr + i * 16) * SA_LD + kk, SA_LD);
                #pragma unroll
                for (int j = 0; j < 2; j++)
                    wmma::mma_sync(acc[i][j], a, b[j], acc[i][j]);
            }
        }
        __syncthreads();
    }

    // -------- fused epilogue --------
    __syncthreads();   // all warps done with pipeline smem
    float* st = (float*)smh + warp * (32 * EP_LD);
    const float scale = (MODE == 0) ? 0.08838834764831843f : 1.0f;

    #pragma unroll
    for (int p = 0; p < 2; ++p) {
        if (p) __syncwarp();
        wmma::store_matrix_sync(st,                 acc[2*p][0],     EP_LD, wmma::mem_row_major);
        wmma::store_matrix_sync(st + 16,            acc[2*p][1],     EP_LD, wmma::mem_row_major);
        wmma::store_matrix_sync(st + 16 * EP_LD,    acc[2*p + 1][0], EP_LD, wmma::mem_row_major);
        wmma::store_matrix_sync(st + 16 * EP_LD + 16, acc[2*p + 1][1], EP_LD, wmma::mem_row_major);
        __syncwarp();

        const int grow = bm + wr + p * 32 + lane;
        const int gc0 = bn + wc;
        const float* srow = st + lane * EP_LD;

        if (MODE == 3) {
            float* O = (float*)out0;
            #pragma unroll
            for (int c = 0; c < 32; c += 4) {
                float4 v;
                v.x = srow[c]     + bias[gc0 + c];
                v.y = srow[c + 1] + bias[gc0 + c + 1];
                v.z = srow[c + 2] + bias[gc0 + c + 2];
                v.w = srow[c + 3] + bias[gc0 + c + 3];
                *(float4*)(O + (size_t)grow * Nn + gc0 + c) = v;
            }
        } else if (MODE == 2) {
            __half* O = (__half*)out0;
            #pragma unroll
            for (int c = 0; c < 32; c += 2) {
                float e = srow[c]     + bias[gc0 + c];
                float o = srow[c + 1] + bias[gc0 + c + 1];
                *(__half2*)(O + (size_t)grow * Nn + gc0 + c) =
                    __halves2half2(__float2half(e), __float2half(o));
            }
        } else {
            const int pos = grow & (SEQ - 1);
            __half* O0 = (__half*)out0;
            __half* O1 = (__half*)out1;
            #pragma unroll
            for (int c = 0; c < 32; c += 2) {
                int gc = gc0 + c;
                float e = srow[c]     + bias[gc];
                float o = srow[c + 1] + bias[gc + 1];
                float2 cs = rope[pos * 64 + ((gc >> 1) & 63)];
                float re = (e * cs.x - o * cs.y) * scale;
                float ro = (o * cs.x + e * cs.y) * scale;
                __half he = __float2half(re), ho = __float2half(ro);
                *(__half2*)(O0 + (size_t)grow * Nn + gc) = __halves2half2(he, ho);
                if (MODE == 0) {
                    *(__half2*)(O1 + (size_t)grow * Nn + gc) = __halves2half2(
                        __float2half(re - __half2float(he)),
                        __float2half(ro - __half2float(ho)));
                }
            }
        }
    }
}

// ---------------- fast exp on FMA pipe ----------------
__device__ __forceinline__ float fexp(float x)
{
    float y = x * 1.4426950408889634f;
    float r = __fadd_rn(y, 12582912.0f);
    float n = __fadd_rn(r, -12582912.0f);
    float f = y - n;
    int e = __float2int_rn(n);
    e = max(e, -126); e = min(e, 126);
    float t = f * 0.6931471805599453f;
    float p = __fmaf_rn(t, 0.0083333333f, 0.041666667f);
    p = __fmaf_rn(t, p, 0.16666667f);
    p = __fmaf_rn(t, p, 0.5f);
    p = __fmaf_rn(t, p, 1.0f);
    p = __fmaf_rn(t, p, 1.0f);
    return p * __int_as_float((e + 127) << 23);
}

// ---------------- tensor-core flash attention ----------------
#define AQ_LD 136
#define AS_LD 72
#define OQH 0
#define OQL (OQH + 64*AQ_LD*2)
#define OKK (OQL + 64*AQ_LD*2)
#define OVV (OKK + 2*64*AQ_LD*2)
#define OPP (OVV + 2*64*AQ_LD*2)
#define OSS (OPP + 64*AS_LD*2)
#define OTT (OSS + 64*AS_LD*4)
#define OOO (OTT + 64*AQ_LD*4)
#define ATT_SMEM (OOO + 64*128*4)

__global__ void __launch_bounds__(128) attn_tc_kernel(
    const __half* __restrict__ Qh, const __half* __restrict__ Ql,
    const __half* __restrict__ K, const __half* __restrict__ V,
    __half* __restrict__ O)
{
    extern __shared__ char smc[];
    __half* sQh = (__half*)(smc + OQH);
    __half* sQl = (__half*)(smc + OQL);
    __half* sK  = (__half*)(smc + OKK);
    __half* sV  = (__half*)(smc + OVV);
    __half* sP  = (__half*)(smc + OPP);
    float*  sS  = (float*)(smc + OSS);
    float*  sT  = (float*)(smc + OTT);
    float*  sO  = (float*)(smc + OOO);

    const int b = blockIdx.y >> 5;
    const int h = blockIdx.y & 31;
    const int kh = h & 3;
    const int q0 = blockIdx.x * 64;
    const int tid = threadIdx.x;
    const int lane = tid & 31;
    const int warp = tid >> 5;

    for (int idx = tid; idx < 64 * 16; idx += 128) {
        int r = idx >> 4, c = (idx & 15) << 3;
        size_t go = (size_t)(b * SEQ + q0 + r) * DMODEL + h * HDIM + c;
        *(uint4*)(sQh + r * AQ_LD + c) = *(const uint4*)(Qh + go);
        *(uint4*)(sQl + r * AQ_LD + c) = *(const uint4*)(Ql + go);
    }
    for (int idx = tid; idx < 64 * 128 / 4; idx += 128) {
        ((float4*)sO)[idx] = make_float4(0.f, 0.f, 0.f, 0.f);
    }

    auto prefetch = [&](int j) {
        int buf = j & 1;
        int k0 = j * 64;
        __half* dk = sK + buf * 64 * AQ_LD;
        __half* dv = sV + buf * 64 * AQ_LD;
        #pragma unroll
        for (int i = 0; i < 8; i++) {
            int idx = tid + i * 128;
            int r = idx >> 4, c = (idx & 15) << 3;
            size_t go = (size_t)(b * SEQ + k0 + r) * KVDIM + kh * HDIM + c;
            cp16(dk + r * AQ_LD + c, K + go);
            cp16(dv + r * AQ_LD + c, V + go);
        }
        asm volatile("cp.async.commit_group;\n");
    };

    prefetch(0);

    const int srow = warp * 16 + (lane >> 1);
    const int shalf = lane & 1;
    float mrow = -1e30f, lrow = 0.f;

    const int jmax = blockIdx.x;
    for (int j = 0; j <= jmax; ++j) {
        asm volatile("cp.async.wait_group 0;\n");
        __syncthreads();
        if (j + 1 <= jmax) prefetch(j + 1);

        __half* cK = sK + (j & 1) * 64 * AQ_LD;
        __half* cV = sV + (j & 1) * 64 * AQ_LD;

        {
            wmma::fragment<wmma::accumulator, 16, 16, 16, float> acc[4];
            #pragma unroll
            for (int nf = 0; nf < 4; nf++) wmma::fill_fragment(acc[nf], 0.f);
            #pragma unroll
            for (int ks = 0; ks < 8; ks++) {
                wmma::fragment<wmma::matrix_a, 16, 16, 16, __half, wmma::row_major> ah, al;
                wmma::load_matrix_sync(ah, sQh + warp * 16 * AQ_LD + ks * 16, AQ_LD);
                wmma::load_matrix_sync(al, sQl + warp * 16 * AQ_LD + ks * 16, AQ_LD);
                #pragma unroll
                for (int nf = 0; nf < 4; nf++) {
                    wmma::fragment<wmma::matrix_b, 16, 16, 16, __half, wmma::col_major> bf;
                    wmma::load_matrix_sync(bf, cK + nf * 16 * AQ_LD + ks * 16, AQ_LD);
                    wmma::mma_sync(acc[nf], ah, bf, acc[nf]);
                    wmma::mma_sync(acc[nf], al, bf, acc[nf]);
                }
            }
            #pragma unroll
            for (int nf = 0; nf < 4; nf++)
                wmma::store_matrix_sync(sS + warp * 16 * AS_LD + nf * 16, acc[nf],
                                        AS_LD, wmma::mem_row_major);
        }
        __syncthreads();

        {
            const int cbase = shalf * 32;
            const bool diag = (j == jmax);
            float sv[32];
            float mx = -1e30f;
            #pragma unroll
            for (int c = 0; c < 32; c++) {
                float s = sS[srow * AS_LD + cbase + c];
                if (diag && (cbase + c > srow)) s = -1e30f;
                sv[c] = s;
                mx = fmaxf(mx, s);
            }
            mx = fmaxf(mx, __shfl_xor_sync(0xffffffffu, mx, 1));
            float mnew = fmaxf(mrow, mx);
            float alpha = fexp(mrow - mnew);
            float sum = 0.f;
            #pragma unroll
            for (int c = 0; c < 32; c++) {
                float p = fexp(sv[c] - mnew);
                sP[srow * AS_LD + cbase + c] = __float2half(p);
                sum += p;
            }
            sum += __shfl_xor_sync(0xffffffffu, sum, 1);
            lrow = lrow * alpha + sum;
            mrow = mnew;
            __syncthreads();

            {
                wmma::fragment<wmma::accumulator, 16, 16, 16, float> acc[8];
                #pragma unroll
                for (int nf = 0; nf < 8; nf++) wmma::fill_fragment(acc[nf], 0.f);
                #pragma unroll
                for (int kf = 0; kf < 4; kf++) {
                    wmma::fragment<wmma::matrix_a, 16, 16, 16, __half, wmma::row_major> af;
                    wmma::load_matrix_sync(af, sP + warp * 16 * AS_LD + kf * 16, AS_LD);
                    #pragma unroll
                    for (int nf = 0; nf < 8; nf++) {
                        wmma::fragment<wmma::matrix_b, 16, 16, 16, __half, wmma::row_major> bf;
                        wmma::load_matrix_sync(bf, cV + kf * 16 * AQ_LD + nf * 16, AQ_LD);
                        wmma::mma_sync(acc[nf], af, bf, acc[nf]);
                    }
                }
                #pragma unroll
                for (int nf = 0; nf < 8; nf++)
                    wmma::store_matrix_sync(sT + warp * 16 * AQ_LD + nf * 16, acc[nf],
                                            AQ_LD, wmma::mem_row_major);
            }
            __syncthreads();

            {
                const int c0 = shalf * 64;
                #pragma unroll
                for (int c = 0; c < 64; c += 4) {
                    float4 o = *(float4*)(sO + srow * 128 + c0 + c);
                    float4 t = *(float4*)(sT + srow * AQ_LD + c0 + c);
                    o.x = o.x * alpha + t.x; o.y = o.y * alpha + t.y;
                    o.z = o.z * alpha + t.z; o.w = o.w * alpha + t.w;
                    *(float4*)(sO + srow * 128 + c0 + c) = o;
                }
            }
            __syncthreads();
        }
    }

    {
        float inv = 1.f / lrow;
        const int c0 = shalf * 64;
        size_t off = (size_t)(b * SEQ + q0 + srow) * DMODEL + h * HDIM + c0;
        #pragma unroll
        for (int c = 0; c < 64; c += 2) {
            float2 o = *(float2*)(sO + srow * 128 + c0 + c);
            *(__half2*)(O + off + c) = __halves2half2(
                __float2half(o.x * inv), __float2half(o.y * inv));
        }
    }
}

// ---------------- launch ----------------
extern "C" void kernel_launch(void* const* d_in, const int* in_sizes, int n_in,
                              void* d_out, int out_size)
{
    const float* x  = (const float*)d_in[0];
    const float* Wq = (const float*)d_in[1];
    const float* bq = (const float*)d_in[2];
    const float* Wk = (const float*)d_in[3];
    const float* bk = (const float*)d_in[4];
    const float* Wv = (const float*)d_in[5];
    const float* bv = (const float*)d_in[6];
    const float* Wo = (const float*)d_in[7];
    const float* bo = (const float*)d_in[8];
    float* out = (float*)d_out;

    __half *xp, *wq, *wk, *wv, *wo, *op, *qh, *ql, *kk, *vv;
    float2* rp;
    cudaGetSymbolAddress((void**)&xp, g_x);
    cudaGetSymbolAddress((void**)&wq, g_wq); cudaGetSymbolAddress((void**)&wk, g_wk);
    cudaGetSymbolAddress((void**)&wv, g_wv); cudaGetSymbolAddress((void**)&wo, g_wo);
    cudaGetSymbolAddress((void**)&op, g_o);
    cudaGetSymbolAddress((void**)&qh, g_Qh); cudaGetSymbolAddress((void**)&ql, g_Ql);
    cudaGetSymbolAddress((void**)&kk, g_Kh); cudaGetSymbolAddress((void**)&vv, g_Vh);
    cudaGetSymbolAddress((void**)&rp, g_rope);

    cudaFuncSetAttribute(gemm_ep_kernel<0>, cudaFuncAttributeMaxDynamicSharedMemorySize, GEMM_SMEM);
    cudaFuncSetAttribute(gemm_ep_kernel<1>, cudaFuncAttributeMaxDynamicSharedMemorySize, GEMM_SMEM);
    cudaFuncSetAttribute(gemm_ep_kernel<2>, cudaFuncAttributeMaxDynamicSharedMemorySize, GEMM_SMEM);
    cudaFuncSetAttribute(gemm_ep_kernel<3>, cudaFuncAttributeMaxDynamicSharedMemorySize, GEMM_SMEM);
    cudaFuncSetAttribute(attn_tc_kernel, cudaFuncAttributeMaxDynamicSharedMemorySize, ATT_SMEM);

    // one-time conversions + rope table
    {
        int n4 = MROWS * DMODEL / 4;
        conv_half_kernel<<<(n4 + 255) / 256, 256>>>(x, xp, n4);
        n4 = DMODEL * DMODEL / 4;
        conv_half_kernel<<<(n4 + 255) / 256, 256>>>(Wq, wq, n4);
        conv_half_kernel<<<(n4 + 255) / 256, 256>>>(Wo, wo, n4);
        n4 = DMODEL * KVDIM / 4;
        conv_half_kernel<<<(n4 + 255) / 256, 256>>>(Wk, wk, n4);
        conv_half_kernel<<<(n4 + 255) / 256, 256>>>(Wv, wv, n4);
        rope_init_kernel<<<(SEQ * 64 + 255) / 256, 256>>>(rp);
    }

    // projections with fused epilogues
    gemm_ep_kernel<0><<<dim3(DMODEL / 128, MROWS / 128), 256, GEMM_SMEM>>>(
        xp, wq, bq, rp, qh, ql, DMODEL, DMODEL);
    gemm_ep_kernel<1><<<dim3(KVDIM / 128, MROWS / 128), 256, GEMM_SMEM>>>(
        xp, wk, bk, rp, kk, nullptr, KVDIM, DMODEL);
    gemm_ep_kernel<2><<<dim3(KVDIM / 128, MROWS / 128), 256, GEMM_SMEM>>>(
        xp, wv, bv, rp, vv, nullptr, KVDIM, DMODEL);

    // attention (tensor cores)
    attn_tc_kernel<<<dim3(SEQ / 64, BATCH * NHEAD), 128, ATT_SMEM>>>(qh, ql, kk, vv, op);

    // output projection with fused bias
    gemm_ep_kernel<3><<<dim3(DMODEL / 128, MROWS / 128), 256, GEMM_SMEM>>>(
        op, wo, bo, rp, out, nullptr, DMODEL, DMODEL);
}